// round 2
// baseline (speedup 1.0000x reference)
#include <cuda_runtime.h>

#define S_LEN 512
#define BATCH 2048
#define DIN 64
#define HID 128

#define RPW 4                    // rows per warp
#define WPC 4                    // warps per CTA
#define RPC (RPW * WPC)          // 16 rows per CTA
#define NTHREADS (WPC * 32)      // 128
#define NCTA (BATCH / RPC)       // 128

typedef unsigned long long u64;

struct __align__(16) Smem {
    float wih_t[DIN][HID];              // 32 KB, transposed W_ih
    float whh_t[HID][HID];              // 64 KB, transposed W_hh
    float xsd[2][WPC][RPW][2 * DIN];    // 16 KB, duplicated x staging (double buf)
    float asd[2][WPC][RPW][2 * HID];    // 32 KB, duplicated a staging (double buf)
};

// packed dual-fp32 FMA: d.lo = a.lo*b.lo + c.lo ; d.hi = a.hi*b.hi + c.hi
__device__ __forceinline__ u64 ffma2(u64 a, u64 b, u64 c) {
    u64 d;
    asm("fma.rn.f32x2 %0, %1, %2, %3;" : "=l"(d) : "l"(a), "l"(b), "l"(c));
    return d;
}
__device__ __forceinline__ u64 pack2(float lo, float hi) {
    u64 d;
    asm("mov.b64 %0, {%1, %2};" : "=l"(d) : "f"(lo), "f"(hi));
    return d;
}
__device__ __forceinline__ void unpack2(u64 v, float& lo, float& hi) {
    asm("mov.b64 {%0, %1}, %2;" : "=f"(lo), "=f"(hi) : "l"(v));
}

__device__ __forceinline__ float fast_tanh(float v) {
    float e = __expf(2.0f * v);
    return 1.0f - __fdividef(2.0f, e + 1.0f);
}

__global__ void __launch_bounds__(NTHREADS, 1)
rnn_kernel(const float* __restrict__ x, const float* __restrict__ h0,
           const float* __restrict__ Wih, const float* __restrict__ bih,
           const float* __restrict__ Whh, const float* __restrict__ bhh,
           float* __restrict__ out)
{
    extern __shared__ Smem smem_raw[];
    Smem& s = smem_raw[0];

    const int tid  = threadIdx.x;
    const int warp = tid >> 5;
    const int lane = tid & 31;
    const int j0   = lane << 2;                       // this lane's 4 output cols
    const int warpRow0 = blockIdx.x * RPC + warp * RPW;

    // ---- stage transposed weights (one-time) ----
    for (int idx = tid; idx < HID * DIN; idx += NTHREADS) {
        int j = idx / DIN, k = idx - j * DIN;
        s.wih_t[k][j] = Wih[idx];
    }
    for (int idx = tid; idx < HID * HID; idx += NTHREADS) {
        int j = idx >> 7, k = idx & 127;
        s.whh_t[k][j] = Whh[idx];
    }

    const float4 bi4 = *(const float4*)(bih + j0);
    const float4 bh4 = *(const float4*)(bhh + j0);
    const u64 bi0 = pack2(bi4.x, bi4.y), bi1 = pack2(bi4.z, bi4.w);
    const u64 bh0 = pack2(bh4.x, bh4.y), bh1 = pack2(bh4.z, bh4.w);

    // ---- h in registers: 4 rows x 4 cols per lane (scalar) ----
    float h[RPW][4];
    #pragma unroll
    for (int r = 0; r < RPW; ++r) {
        float4 hv = *(const float4*)(h0 + (size_t)(warpRow0 + r) * HID + j0);
        h[r][0] = hv.x; h[r][1] = hv.y; h[r][2] = hv.z; h[r][3] = hv.w;
    }

    // lane's slice of the warp's 4x64 x block: linear idx lane*4 (+128)
    const int xr0 = lane >> 4;                 // row 0..1
    const int xk0 = (lane << 2) & 63;          // k offset, multiple of 4

    // ---- prologue: load x(t=0), stage duplicated into buf 0, prefetch x(t=1)
    float4 xn0, xn1;
    {
        const float4* p = (const float4*)(x + (size_t)warpRow0 * DIN);
        xn0 = p[lane]; xn1 = p[lane + 32];
        float4* d0 = (float4*)&s.xsd[0][warp][xr0][2 * xk0];
        d0[0] = make_float4(xn0.x, xn0.x, xn0.y, xn0.y);
        d0[1] = make_float4(xn0.z, xn0.z, xn0.w, xn0.w);
        float4* d1 = (float4*)&s.xsd[0][warp][xr0 + 2][2 * xk0];
        d1[0] = make_float4(xn1.x, xn1.x, xn1.y, xn1.y);
        d1[1] = make_float4(xn1.z, xn1.z, xn1.w, xn1.w);
        const float4* pn = (const float4*)(x + ((size_t)BATCH + warpRow0) * DIN);
        xn0 = pn[lane]; xn1 = pn[lane + 32];
    }
    __syncthreads();   // weights + x(0) staged

    for (int t = 0; t < S_LEN; ++t) {
        const int buf = t & 1;

        // ---- GEMM1: acc = x_t @ W_ih^T + b_ih  (packed f32x2) ----
        u64 acc0[RPW], acc1[RPW];
        #pragma unroll
        for (int r = 0; r < RPW; ++r) { acc0[r] = bi0; acc1[r] = bi1; }

        const float* xrow = &s.xsd[buf][warp][0][0];
        #pragma unroll 4
        for (int k = 0; k < DIN; k += 2) {
            const u64* w0 = (const u64*)&s.wih_t[k][j0];
            const u64* w1 = (const u64*)&s.wih_t[k + 1][j0];
            u64 xv0[RPW], xv1[RPW];
            #pragma unroll
            for (int r = 0; r < RPW; ++r) {
                const u64* xp = (const u64*)(xrow + r * (2 * DIN) + 2 * k);
                xv0[r] = xp[0]; xv1[r] = xp[1];
            }
            #pragma unroll
            for (int r = 0; r < RPW; ++r) {
                acc0[r] = ffma2(xv0[r], w0[0], acc0[r]);
                acc1[r] = ffma2(xv0[r], w0[1], acc1[r]);
            }
            #pragma unroll
            for (int r = 0; r < RPW; ++r) {
                acc0[r] = ffma2(xv1[r], w1[0], acc0[r]);
                acc1[r] = ffma2(xv1[r], w1[1], acc1[r]);
            }
        }

        // ---- a = acc * h ; stage duplicated a ----
        float a[RPW][4];
        #pragma unroll
        for (int r = 0; r < RPW; ++r) {
            float v0, v1, v2, v3;
            unpack2(acc0[r], v0, v1);
            unpack2(acc1[r], v2, v3);
            a[r][0] = v0 * h[r][0];
            a[r][1] = v1 * h[r][1];
            a[r][2] = v2 * h[r][2];
            a[r][3] = v3 * h[r][3];
            float4* ad = (float4*)&s.asd[buf][warp][r][2 * j0];
            ad[0] = make_float4(a[r][0], a[r][0], a[r][1], a[r][1]);
            ad[1] = make_float4(a[r][2], a[r][2], a[r][3], a[r][3]);
        }

        // ---- stage duplicated x for t+1 into other buffer, prefetch t+2 ----
        {
            float4* d0 = (float4*)&s.xsd[buf ^ 1][warp][xr0][2 * xk0];
            d0[0] = make_float4(xn0.x, xn0.x, xn0.y, xn0.y);
            d0[1] = make_float4(xn0.z, xn0.z, xn0.w, xn0.w);
            float4* d1 = (float4*)&s.xsd[buf ^ 1][warp][xr0 + 2][2 * xk0];
            d1[0] = make_float4(xn1.x, xn1.x, xn1.y, xn1.y);
            d1[1] = make_float4(xn1.z, xn1.z, xn1.w, xn1.w);
            const int tn = (t + 2 < S_LEN) ? t + 2 : t;
            const float4* p = (const float4*)(x + ((size_t)tn * BATCH + warpRow0) * DIN);
            xn0 = p[lane]; xn1 = p[lane + 32];
        }
        __syncwarp();   // a-dup (this step) + x-dup (next step) visible

        // ---- GEMM2: acc2 = a @ W_hh^T + b_hh  (packed f32x2) ----
        u64 acc20[RPW], acc21[RPW];
        #pragma unroll
        for (int r = 0; r < RPW; ++r) { acc20[r] = bh0; acc21[r] = bh1; }

        const float* arow = &s.asd[buf][warp][0][0];
        #pragma unroll 4
        for (int k = 0; k < HID; k += 2) {
            const u64* w0 = (const u64*)&s.whh_t[k][j0];
            const u64* w1 = (const u64*)&s.whh_t[k + 1][j0];
            u64 av0[RPW], av1[RPW];
            #pragma unroll
            for (int r = 0; r < RPW; ++r) {
                const u64* ap = (const u64*)(arow + r * (2 * HID) + 2 * k);
                av0[r] = ap[0]; av1[r] = ap[1];
            }
            #pragma unroll
            for (int r = 0; r < RPW; ++r) {
                acc20[r] = ffma2(av0[r], w0[0], acc20[r]);
                acc21[r] = ffma2(av0[r], w0[1], acc21[r]);
            }
            #pragma unroll
            for (int r = 0; r < RPW; ++r) {
                acc20[r] = ffma2(av1[r], w1[0], acc20[r]);
                acc21[r] = ffma2(av1[r], w1[1], acc21[r]);
            }
        }

        // ---- h' = tanh(a + acc2 * h) ----
        #pragma unroll
        for (int r = 0; r < RPW; ++r) {
            float v0, v1, v2, v3;
            unpack2(acc20[r], v0, v1);
            unpack2(acc21[r], v2, v3);
            h[r][0] = fast_tanh(fmaf(v0, h[r][0], a[r][0]));
            h[r][1] = fast_tanh(fmaf(v1, h[r][1], a[r][1]));
            h[r][2] = fast_tanh(fmaf(v2, h[r][2], a[r][2]));
            h[r][3] = fast_tanh(fmaf(v3, h[r][3], a[r][3]));
        }
    }

    // ---- write final hidden state ----
    #pragma unroll
    for (int r = 0; r < RPW; ++r)
        *(float4*)(out + (size_t)(warpRow0 + r) * HID + j0) =
            make_float4(h[r][0], h[r][1], h[r][2], h[r][3]);
}

extern "C" void kernel_launch(void* const* d_in, const int* in_sizes, int n_in,
                              void* d_out, int out_size)
{
    const float* x   = (const float*)d_in[0];
    const float* h0  = (const float*)d_in[1];
    const float* Wih = (const float*)d_in[2];
    const float* bih = (const float*)d_in[3];
    const float* Whh = (const float*)d_in[4];
    const float* bhh = (const float*)d_in[5];

    cudaFuncSetAttribute(rnn_kernel, cudaFuncAttributeMaxDynamicSharedMemorySize,
                         (int)sizeof(Smem));
    rnn_kernel<<<NCTA, NTHREADS, sizeof(Smem)>>>(x, h0, Wih, bih, Whh, bhh,
                                                 (float*)d_out);
}

// round 3
// speedup vs baseline: 1.7233x; 1.7233x over previous
#include <cuda_runtime.h>

#define S_LEN 512
#define BATCH 2048
#define DIN 64
#define HID 128

#define RPW 4                    // rows per warp
#define WPC 4                    // warps per CTA
#define RPC (RPW * WPC)          // 16 rows per CTA
#define NTHREADS (WPC * 32)      // 128
#define NCTA (BATCH / RPC)       // 128

typedef unsigned long long u64;

struct __align__(16) Smem {
    float wih_t[DIN][HID];            // 32 KB, transposed W_ih
    float whh_t[HID][HID];            // 64 KB, transposed W_hh
    float xs[2][WPC][RPW][DIN];       // 8 KB, double-buffered x staging
    float as[WPC][RPW][HID];          // 8 KB, a staging for GEMM2 broadcast
};

// packed dual-fp32 FMA: d.lo = a.lo*b.lo + c.lo ; d.hi = a.hi*b.hi + c.hi
__device__ __forceinline__ u64 ffma2(u64 a, u64 b, u64 c) {
    u64 d;
    asm("fma.rn.f32x2 %0, %1, %2, %3;" : "=l"(d) : "l"(a), "l"(b), "l"(c));
    return d;
}
__device__ __forceinline__ u64 dup2(float v) {      // (v, v) — 2 MOVs on ALU pipe
    u64 d;
    asm("mov.b64 %0, {%1, %1};" : "=l"(d) : "f"(v));
    return d;
}
__device__ __forceinline__ u64 pack2(float lo, float hi) {
    u64 d;
    asm("mov.b64 %0, {%1, %2};" : "=l"(d) : "f"(lo), "f"(hi));
    return d;
}
__device__ __forceinline__ void unpack2(u64 v, float& lo, float& hi) {
    asm("mov.b64 {%0, %1}, %2;" : "=f"(lo), "=f"(hi) : "l"(v));
}

__device__ __forceinline__ float fast_tanh(float v) {
    float e = __expf(2.0f * v);
    return 1.0f - __fdividef(2.0f, e + 1.0f);
}

__global__ void __launch_bounds__(NTHREADS, 1)
rnn_kernel(const float* __restrict__ x, const float* __restrict__ h0,
           const float* __restrict__ Wih, const float* __restrict__ bih,
           const float* __restrict__ Whh, const float* __restrict__ bhh,
           float* __restrict__ out)
{
    extern __shared__ Smem smem_raw[];
    Smem& s = smem_raw[0];

    const int tid  = threadIdx.x;
    const int warp = tid >> 5;
    const int lane = tid & 31;
    const int j0   = lane << 2;                       // this lane's 4 output cols
    const int warpRow0 = blockIdx.x * RPC + warp * RPW;

    // ---- stage transposed weights (one-time) ----
    for (int idx = tid; idx < HID * DIN; idx += NTHREADS) {
        int j = idx / DIN, k = idx - j * DIN;
        s.wih_t[k][j] = Wih[idx];
    }
    for (int idx = tid; idx < HID * HID; idx += NTHREADS) {
        int j = idx >> 7, k = idx & 127;
        s.whh_t[k][j] = Whh[idx];
    }

    const float4 bi4 = *(const float4*)(bih + j0);
    const float4 bh4 = *(const float4*)(bhh + j0);
    const u64 bi0 = pack2(bi4.x, bi4.y), bi1 = pack2(bi4.z, bi4.w);
    const u64 bh0 = pack2(bh4.x, bh4.y), bh1 = pack2(bh4.z, bh4.w);

    // ---- h in registers: 4 rows x 4 cols per lane ----
    float h[RPW][4];
    #pragma unroll
    for (int r = 0; r < RPW; ++r) {
        float4 hv = *(const float4*)(h0 + (size_t)(warpRow0 + r) * HID + j0);
        h[r][0] = hv.x; h[r][1] = hv.y; h[r][2] = hv.z; h[r][3] = hv.w;
    }

    // ---- prefetch x for t=0 ----
    float4 xn0, xn1;
    {
        const float4* p = (const float4*)(x + (size_t)warpRow0 * DIN);
        xn0 = p[lane]; xn1 = p[lane + 32];
    }
    __syncthreads();

    for (int t = 0; t < S_LEN; ++t) {
        const int buf = t & 1;

        // commit staged x, then prefetch t+1
        {
            float4* xs4 = (float4*)&s.xs[buf][warp][0][0];
            xs4[lane] = xn0; xs4[lane + 32] = xn1;
        }
        __syncwarp();
        {
            const int tn = (t + 1 < S_LEN) ? t + 1 : t;
            const float4* p = (const float4*)(x + ((size_t)tn * BATCH + warpRow0) * DIN);
            xn0 = p[lane]; xn1 = p[lane + 32];
        }

        // ---- GEMM1: acc = x_t @ W_ih^T + b_ih  (f32x2 accumulators) ----
        u64 acc0[RPW], acc1[RPW];
        #pragma unroll
        for (int r = 0; r < RPW; ++r) { acc0[r] = bi0; acc1[r] = bi1; }

        #pragma unroll 2
        for (int k4 = 0; k4 < DIN / 4; ++k4) {
            float xv[RPW][4];
            #pragma unroll
            for (int r = 0; r < RPW; ++r)
                *(float4*)xv[r] = *(const float4*)&s.xs[buf][warp][r][k4 * 4];
            #pragma unroll
            for (int kk = 0; kk < 4; ++kk) {
                const u64* w = (const u64*)&s.wih_t[k4 * 4 + kk][j0];  // one LDS.128
                const u64 w0 = w[0], w1 = w[1];
                #pragma unroll
                for (int r = 0; r < RPW; ++r) {
                    const u64 xd = dup2(xv[r][kk]);
                    acc0[r] = ffma2(xd, w0, acc0[r]);
                    acc1[r] = ffma2(xd, w1, acc1[r]);
                }
            }
        }

        // ---- a = acc * h ; stage a (scalar layout, as round 1) ----
        float a[RPW][4];
        #pragma unroll
        for (int r = 0; r < RPW; ++r) {
            float v0, v1, v2, v3;
            unpack2(acc0[r], v0, v1);
            unpack2(acc1[r], v2, v3);
            a[r][0] = v0 * h[r][0];
            a[r][1] = v1 * h[r][1];
            a[r][2] = v2 * h[r][2];
            a[r][3] = v3 * h[r][3];
            *(float4*)&s.as[warp][r][j0] = make_float4(a[r][0], a[r][1], a[r][2], a[r][3]);
        }
        __syncwarp();

        // ---- GEMM2: acc2 = a @ W_hh^T + b_hh  (f32x2 accumulators) ----
        u64 acc20[RPW], acc21[RPW];
        #pragma unroll
        for (int r = 0; r < RPW; ++r) { acc20[r] = bh0; acc21[r] = bh1; }

        #pragma unroll 2
        for (int k4 = 0; k4 < HID / 4; ++k4) {
            float av[RPW][4];
            #pragma unroll
            for (int r = 0; r < RPW; ++r)
                *(float4*)av[r] = *(const float4*)&s.as[warp][r][k4 * 4];
            #pragma unroll
            for (int kk = 0; kk < 4; ++kk) {
                const u64* w = (const u64*)&s.whh_t[k4 * 4 + kk][j0];  // one LDS.128
                const u64 w0 = w[0], w1 = w[1];
                #pragma unroll
                for (int r = 0; r < RPW; ++r) {
                    const u64 ad = dup2(av[r][kk]);
                    acc20[r] = ffma2(ad, w0, acc20[r]);
                    acc21[r] = ffma2(ad, w1, acc21[r]);
                }
            }
        }

        // ---- h' = tanh(a + acc2 * h) ----
        #pragma unroll
        for (int r = 0; r < RPW; ++r) {
            float v0, v1, v2, v3;
            unpack2(acc20[r], v0, v1);
            unpack2(acc21[r], v2, v3);
            h[r][0] = fast_tanh(fmaf(v0, h[r][0], a[r][0]));
            h[r][1] = fast_tanh(fmaf(v1, h[r][1], a[r][1]));
            h[r][2] = fast_tanh(fmaf(v2, h[r][2], a[r][2]));
            h[r][3] = fast_tanh(fmaf(v3, h[r][3], a[r][3]));
        }
    }

    // ---- write final hidden state ----
    #pragma unroll
    for (int r = 0; r < RPW; ++r)
        *(float4*)(out + (size_t)(warpRow0 + r) * HID + j0) =
            make_float4(h[r][0], h[r][1], h[r][2], h[r][3]);
}

extern "C" void kernel_launch(void* const* d_in, const int* in_sizes, int n_in,
                              void* d_out, int out_size)
{
    const float* x   = (const float*)d_in[0];
    const float* h0  = (const float*)d_in[1];
    const float* Wih = (const float*)d_in[2];
    const float* bih = (const float*)d_in[3];
    const float* Whh = (const float*)d_in[4];
    const float* bhh = (const float*)d_in[5];

    cudaFuncSetAttribute(rnn_kernel, cudaFuncAttributeMaxDynamicSharedMemorySize,
                         (int)sizeof(Smem));
    rnn_kernel<<<NCTA, NTHREADS, sizeof(Smem)>>>(x, h0, Wih, bih, Whh, bhh,
                                                 (float*)d_out);
}